// round 1
// baseline (speedup 1.0000x reference)
#include <cuda_runtime.h>

#define S_LEN 2048
#define HID 2048
#define NH 32
#define NKV 8
#define HD 64
#define QKV_OUT 3072   // (32 + 2*8) * 64

// ---------------- scratch (static device globals; no allocation) ----------------
__device__ float g_qkv[S_LEN * QKV_OUT];      // [s][o]          25.2 MB
__device__ float g_q[NH * S_LEN * HD];        // [h][s][d]       16.8 MB
__device__ float g_k[NKV * S_LEN * HD];       // [kh][s][d]       4.2 MB
__device__ float g_v[NKV * S_LEN * HD];       // [kh][s][d]       4.2 MB
__device__ float g_attn[S_LEN * NH * HD];     // [s][h*64+d]     16.8 MB

// =====================================================================
// Generic NT SGEMM: C[M,N] = A[M,K] * B[N,K]^T, all K-contiguous row-major.
// 128x128 block tile, BK=8, 256 threads, 8x8 micro-tile, float4 everywhere.
// Requires M%128==0, N%128==0, K%8==0 (true for all our shapes).
// =====================================================================
__global__ __launch_bounds__(256) void sgemm_nt(const float* __restrict__ A,
                                                const float* __restrict__ B,
                                                float* __restrict__ C,
                                                int N, int K) {
    __shared__ float As[8][128];
    __shared__ float Bs[8][128];

    const int tid = threadIdx.x;
    const int bm = blockIdx.y * 128;
    const int bn = blockIdx.x * 128;

    const int lrow = tid >> 1;          // 0..127 : row within tile for loads
    const int lk   = (tid & 1) << 2;    // 0 or 4 : k offset for loads

    const int tr = (tid >> 4) << 3;     // 0..120 : micro-tile row
    const int tc = (tid & 15) << 3;     // 0..120 : micro-tile col

    const float* Aptr = A + (size_t)(bm + lrow) * K + lk;
    const float* Bptr = B + (size_t)(bn + lrow) * K + lk;

    float acc[8][8];
#pragma unroll
    for (int i = 0; i < 8; i++)
#pragma unroll
        for (int j = 0; j < 8; j++) acc[i][j] = 0.f;

    for (int k0 = 0; k0 < K; k0 += 8) {
        float4 av = *(const float4*)(Aptr + k0);
        float4 bv = *(const float4*)(Bptr + k0);
        As[lk + 0][lrow] = av.x; As[lk + 1][lrow] = av.y;
        As[lk + 2][lrow] = av.z; As[lk + 3][lrow] = av.w;
        Bs[lk + 0][lrow] = bv.x; Bs[lk + 1][lrow] = bv.y;
        Bs[lk + 2][lrow] = bv.z; Bs[lk + 3][lrow] = bv.w;
        __syncthreads();

#pragma unroll
        for (int kk = 0; kk < 8; kk++) {
            float a[8], b[8];
            *(float4*)(a)     = *(const float4*)&As[kk][tr];
            *(float4*)(a + 4) = *(const float4*)&As[kk][tr + 4];
            *(float4*)(b)     = *(const float4*)&Bs[kk][tc];
            *(float4*)(b + 4) = *(const float4*)&Bs[kk][tc + 4];
#pragma unroll
            for (int i = 0; i < 8; i++)
#pragma unroll
                for (int j = 0; j < 8; j++)
                    acc[i][j] += a[i] * b[j];
        }
        __syncthreads();
    }

#pragma unroll
    for (int i = 0; i < 8; i++) {
        float* crow = C + (size_t)(bm + tr + i) * N + bn + tc;
        *(float4*)(crow)     = *(float4*)&acc[i][0];
        *(float4*)(crow + 4) = *(float4*)&acc[i][4];
    }
}

// =====================================================================
// RoPE + split + [h][s][d] transpose.
// qkv[s][o], o = hh*64+d; hh<32 -> q (rope), 32..39 -> k (rope), 40..47 -> v.
// =====================================================================
__global__ __launch_bounds__(256) void rope_split(const float* __restrict__ qkv,
                                                  const float* __restrict__ cosb,
                                                  const float* __restrict__ sinb) {
    int idx = blockIdx.x * 256 + threadIdx.x;
    if (idx >= S_LEN * QKV_OUT) return;
    int s = idx / QKV_OUT;
    int o = idx - s * QKV_OUT;
    int hh = o >> 6;
    int d  = o & 63;
    float val = qkv[idx];
    if (hh < NH + NKV) {
        float c  = cosb[s * HD + d];
        float sn = sinb[s * HD + d];
        int dpair = (d < 32) ? d + 32 : d - 32;
        float other = qkv[s * QKV_OUT + (hh << 6) + dpair];
        float rot = (d < 32) ? -other : other;
        float r = val * c + rot * sn;
        if (hh < NH) g_q[((hh * S_LEN + s) << 6) + d] = r;
        else         g_k[(((hh - NH) * S_LEN + s) << 6) + d] = r;
    } else {
        g_v[(((hh - NH - NKV) * S_LEN + s) << 6) + d] = val;
    }
}

// =====================================================================
// fp32 flash attention, causal, GQA (4 q-heads per kv-head).
// grid = (32 q-blocks, 32 heads); block = 256 threads = 16x16, 4x4 micro.
// Tiles: 64 query rows x 64 key cols, head_dim 64.
// smem (dynamic 68608B): Qs/Ks/Ps transposed [64][68], Vs natural [64][64].
// =====================================================================
#define PADT 68
#define ATTN_SMEM ((3 * 64 * PADT + 64 * 64) * 4)

__global__ __launch_bounds__(256) void flash_attn(float* __restrict__ Og) {
    extern __shared__ float sm[];
    float* Qs = sm;                    // [d][r]  stride PADT
    float* Ks = Qs + 64 * PADT;        // [d][c]  stride PADT
    float* Ps = Ks + 64 * PADT;        // [j][r]  stride PADT
    float* Vs = Ps + 64 * PADT;        // [j][dv] stride 64

    const int qb = blockIdx.x;
    const int h  = blockIdx.y;
    const float* Qh = g_q + (size_t)(h * S_LEN + qb * 64) * HD;
    const float* Kh = g_k + (size_t)((h >> 2) * S_LEN) * HD;
    const float* Vh = g_v + (size_t)((h >> 2) * S_LEN) * HD;

    const int tid = threadIdx.x;
    const int lr  = tid >> 4;           // 0..15 load row
    const int ld4 = (tid & 15) << 2;    // 0..60 load d (float4)
    const int ty = tid >> 4, tx = tid & 15;
    const int tr = ty << 2, tc = tx << 2;

    // load Q tile (transposed, padded)
#pragma unroll
    for (int it = 0; it < 4; it++) {
        int r = lr + it * 16;
        float4 qv = *(const float4*)(Qh + r * HD + ld4);
        Qs[(ld4 + 0) * PADT + r] = qv.x;
        Qs[(ld4 + 1) * PADT + r] = qv.y;
        Qs[(ld4 + 2) * PADT + r] = qv.z;
        Qs[(ld4 + 3) * PADT + r] = qv.w;
    }

    float m[4], l[4], o[4][4];
#pragma unroll
    for (int i = 0; i < 4; i++) {
        m[i] = -1e30f; l[i] = 0.f;
#pragma unroll
        for (int j = 0; j < 4; j++) o[i][j] = 0.f;
    }
    __syncthreads();

    const float scale = 0.125f;  // 1/sqrt(64)
    const unsigned FULL = 0xffffffffu;

    for (int kb = 0; kb <= qb; kb++) {
        // load K (transposed) and V (natural) tiles
#pragma unroll
        for (int it = 0; it < 4; it++) {
            int r = lr + it * 16;
            float4 kv = *(const float4*)(Kh + (size_t)(kb * 64 + r) * HD + ld4);
            Ks[(ld4 + 0) * PADT + r] = kv.x;
            Ks[(ld4 + 1) * PADT + r] = kv.y;
            Ks[(ld4 + 2) * PADT + r] = kv.z;
            Ks[(ld4 + 3) * PADT + r] = kv.w;
            float4 vv = *(const float4*)(Vh + (size_t)(kb * 64 + r) * HD + ld4);
            *(float4*)&Vs[r * 64 + ld4] = vv;
        }
        __syncthreads();

        // S = Q K^T  (4x4 micro-tile)
        float s4[4][4];
#pragma unroll
        for (int i = 0; i < 4; i++)
#pragma unroll
            for (int j = 0; j < 4; j++) s4[i][j] = 0.f;
#pragma unroll 16
        for (int d = 0; d < 64; d++) {
            float4 a = *(const float4*)&Qs[d * PADT + tr];
            float4 b = *(const float4*)&Ks[d * PADT + tc];
            float av[4] = {a.x, a.y, a.z, a.w};
            float bv[4] = {b.x, b.y, b.z, b.w};
#pragma unroll
            for (int i = 0; i < 4; i++)
#pragma unroll
                for (int j = 0; j < 4; j++)
                    s4[i][j] += av[i] * bv[j];
        }

        // scale + causal mask (only diagonal block has partial mask)
        if (kb == qb) {
#pragma unroll
            for (int i = 0; i < 4; i++)
#pragma unroll
                for (int j = 0; j < 4; j++)
                    s4[i][j] = (tc + j > tr + i) ? -1e30f : s4[i][j] * scale;
        } else {
#pragma unroll
            for (int i = 0; i < 4; i++)
#pragma unroll
                for (int j = 0; j < 4; j++) s4[i][j] *= scale;
        }

        // online softmax
        float p[4][4];
#pragma unroll
        for (int i = 0; i < 4; i++) {
            float mt = fmaxf(fmaxf(s4[i][0], s4[i][1]), fmaxf(s4[i][2], s4[i][3]));
#pragma unroll
            for (int off = 8; off >= 1; off >>= 1)
                mt = fmaxf(mt, __shfl_xor_sync(FULL, mt, off));
            float mn = fmaxf(m[i], mt);
            float corr = __expf(m[i] - mn);
            float rs = 0.f;
#pragma unroll
            for (int j = 0; j < 4; j++) {
                p[i][j] = __expf(s4[i][j] - mn);
                rs += p[i][j];
            }
#pragma unroll
            for (int off = 8; off >= 1; off >>= 1)
                rs += __shfl_xor_sync(FULL, rs, off);
            l[i] = l[i] * corr + rs;
            m[i] = mn;
#pragma unroll
            for (int j = 0; j < 4; j++) o[i][j] *= corr;
        }

        // write P^T to smem
        __syncthreads();
#pragma unroll
        for (int i = 0; i < 4; i++)
#pragma unroll
            for (int j = 0; j < 4; j++)
                Ps[(tc + j) * PADT + (tr + i)] = p[i][j];
        __syncthreads();

        // O += P V
#pragma unroll 16
        for (int j = 0; j < 64; j++) {
            float4 a = *(const float4*)&Ps[j * PADT + tr];
            float4 b = *(const float4*)&Vs[j * 64 + tc];
            float av[4] = {a.x, a.y, a.z, a.w};
            float bv[4] = {b.x, b.y, b.z, b.w};
#pragma unroll
            for (int i = 0; i < 4; i++)
#pragma unroll
                for (int jj = 0; jj < 4; jj++)
                    o[i][jj] += av[i] * bv[jj];
        }
        __syncthreads();
    }

    // normalize + write to g_attn[s][h*64+d]
#pragma unroll
    for (int i = 0; i < 4; i++) {
        float inv = 1.f / l[i];
        float4 outv = make_float4(o[i][0] * inv, o[i][1] * inv,
                                  o[i][2] * inv, o[i][3] * inv);
        *(float4*)&Og[(size_t)(qb * 64 + tr + i) * (NH * HD) + h * HD + tc] = outv;
    }
}

// =====================================================================
extern "C" void kernel_launch(void* const* d_in, const int* in_sizes, int n_in,
                              void* d_out, int out_size) {
    const float* x     = (const float*)d_in[0];
    const float* cosb  = (const float*)d_in[1];
    const float* sinb  = (const float*)d_in[2];
    const float* w_qkv = (const float*)d_in[3];
    const float* w_out = (const float*)d_in[4];
    float* out = (float*)d_out;

    float *qkv_p, *attn_p;
    cudaGetSymbolAddress((void**)&qkv_p, g_qkv);
    cudaGetSymbolAddress((void**)&attn_p, g_attn);

    cudaFuncSetAttribute(flash_attn, cudaFuncAttributeMaxDynamicSharedMemorySize,
                         ATTN_SMEM);

    // 1) QKV projection: [2048,3072] = x[2048,2048] @ w_qkv[3072,2048]^T
    sgemm_nt<<<dim3(QKV_OUT / 128, S_LEN / 128), 256>>>(x, w_qkv, qkv_p,
                                                        QKV_OUT, HID);
    // 2) RoPE + split + transpose
    rope_split<<<(S_LEN * QKV_OUT + 255) / 256, 256>>>(qkv_p, cosb, sinb);
    // 3) causal flash attention
    flash_attn<<<dim3(S_LEN / 64, NH), 256, ATTN_SMEM>>>(attn_p);
    // 4) output projection: [2048,2048] = attn[2048,2048] @ w_out[2048,2048]^T
    sgemm_nt<<<dim3(HID / 128, S_LEN / 128), 256>>>(attn_p, w_out, out,
                                                    HID, NH * HD);
}

// round 3
// speedup vs baseline: 1.7927x; 1.7927x over previous
#include <cuda_runtime.h>
#include <cuda_bf16.h>
#include <cstdint>

#define S_LEN 2048
#define HID 2048
#define NH 32
#define NKV 8
#define HD 64
#define QKV_OUT 3072   // (32 + 2*8) * 64

// ---------------- scratch (static device globals; no allocation) ----------------
__device__ float g_qkv[S_LEN * QKV_OUT];      // [s][o]
__device__ float g_q[NH * S_LEN * HD];        // [h][s][d]
__device__ float g_k[NKV * S_LEN * HD];       // [kh][s][d]
__device__ float g_v[NKV * S_LEN * HD];       // [kh][s][d]
__device__ float g_attn[S_LEN * NH * HD];     // [s][h*64+d]

// bf16 split operands
__device__ __nv_bfloat16 g_xh[S_LEN * HID],     g_xl[S_LEN * HID];
__device__ __nv_bfloat16 g_wqh[QKV_OUT * HID],  g_wql[QKV_OUT * HID];
__device__ __nv_bfloat16 g_woh[HID * HID],      g_wol[HID * HID];
__device__ __nv_bfloat16 g_ah[S_LEN * HID],     g_al[S_LEN * HID];

// ============================ helpers ============================
__device__ __forceinline__ uint32_t smem_u32(const void* p) {
    uint32_t a;
    asm("{ .reg .u64 t; cvta.to.shared.u64 t, %1; cvt.u32.u64 %0, t; }"
        : "=r"(a) : "l"(p));
    return a;
}
__device__ __forceinline__ void cp16(uint32_t s, const void* g) {
    asm volatile("cp.async.cg.shared.global [%0], [%1], 16;" :: "r"(s), "l"(g));
}
#define CP_COMMIT() asm volatile("cp.async.commit_group;" ::: "memory")

__device__ __forceinline__ void ldmx4(uint32_t* r, uint32_t addr) {
    asm volatile("ldmatrix.sync.aligned.m8n8.x4.shared.b16 {%0,%1,%2,%3}, [%4];"
                 : "=r"(r[0]), "=r"(r[1]), "=r"(r[2]), "=r"(r[3]) : "r"(addr));
}
__device__ __forceinline__ void mma16816(float* d, const uint32_t* a,
                                         const uint32_t* b) {
    asm volatile(
        "mma.sync.aligned.m16n8k16.row.col.f32.bf16.bf16.f32 "
        "{%0,%1,%2,%3}, {%4,%5,%6,%7}, {%8,%9}, {%0,%1,%2,%3};"
        : "+f"(d[0]), "+f"(d[1]), "+f"(d[2]), "+f"(d[3])
        : "r"(a[0]), "r"(a[1]), "r"(a[2]), "r"(a[3]), "r"(b[0]), "r"(b[1]));
}

// ============================================================================
// Split-precision bf16 GEMM on mma.sync (HMMA):
//   C[M,N] = A[M,K] * B[N,K]^T,  A = Ah+Al, B = Bh+Bl,
//   accum Ah*Bh + Ah*Bl + Al*Bh in fp32 (drops lo*lo ~2^-18).
// 128x128 CTA tile, BK=32, 8 warps (4x2), warp tile 32x64 (2x8 m16n8k16 atoms).
// 2-stage cp.async pipeline. smem rows padded to 80B (conflict-free ldmatrix).
// ============================================================================
#define BK 32
#define ROWB 80                         // bytes per smem row (64B data + 16B pad)
#define TILE_B (128 * ROWB)             // 10240
#define STAGE_B (4 * TILE_B)            // Ah, Al, Bh, Bl  = 40960
#define GEMM_SMEM (2 * STAGE_B)         // 81920

__global__ __launch_bounds__(256, 2) void gemm_mma(
    const __nv_bfloat16* __restrict__ Ah, const __nv_bfloat16* __restrict__ Al,
    const __nv_bfloat16* __restrict__ Bh, const __nv_bfloat16* __restrict__ Bl,
    float* __restrict__ C, int N, int K) {
    extern __shared__ __align__(128) char dsm[];
    const uint32_t base = smem_u32(dsm);

    const int tid = threadIdx.x;
    const int wid = tid >> 5;
    const int lane = tid & 31;
    const int wm = wid >> 1;            // 0..3 : warp row
    const int wn = wid & 1;             // 0..1 : warp col
    const int bm = blockIdx.y * 128;
    const int bn = blockIdx.x * 128;
    const int nchunk = K / BK;

    float acc[2][8][4];
#pragma unroll
    for (int i = 0; i < 2; i++)
#pragma unroll
        for (int j = 0; j < 8; j++)
#pragma unroll
            for (int k = 0; k < 4; k++) acc[i][j][k] = 0.f;

    // ---- global -> smem loader (one BK-chunk of all 4 tiles) ----
    auto load_chunk = [&](int chunk, int stage) {
        const int k0 = chunk * BK;
        const uint32_t sb = base + stage * STAGE_B;
#pragma unroll
        for (int t = 0; t < 4; t++) {
            const __nv_bfloat16* src = (t == 0) ? Ah : (t == 1) ? Al
                                     : (t == 2) ? Bh : Bl;
            const int rowbase = (t < 2) ? bm : bn;
            const uint32_t tb = sb + t * TILE_B;
#pragma unroll
            for (int i = 0; i < 2; i++) {
                int c = tid + i * 256;        // 0..511
                int r = c >> 2;               // row 0..127
                int cc = c & 3;               // 16B chunk in row
                cp16(tb + r * ROWB + cc * 16,
                     src + (size_t)(rowbase + r) * K + k0 + cc * 8);
            }
        }
        CP_COMMIT();
    };

    // ldmatrix lane addressing
    const int a_row = (lane & 15);            // row within 16-row atom
    const int a_kh  = (lane >> 4);            // k-half (16B)
    const int b_row = (lane & 7) + ((lane >> 4) << 3);  // row within 16-n pair
    const int b_kh  = (lane >> 3) & 1;

    auto compute = [&](int stage) {
        const uint32_t sb  = base + stage * STAGE_B;
        const uint32_t sAh = sb;
        const uint32_t sAl = sb + TILE_B;
        const uint32_t sBh = sb + 2 * TILE_B;
        const uint32_t sBl = sb + 3 * TILE_B;
#pragma unroll
        for (int ks = 0; ks < 2; ks++) {
            const uint32_t ko = ks * 32 + a_kh * 16;
            uint32_t afh[2][4], afl[2][4];
#pragma unroll
            for (int ma = 0; ma < 2; ma++) {
                const uint32_t ro = (uint32_t)(wm * 32 + ma * 16 + a_row) * ROWB;
                ldmx4(afh[ma], sAh + ro + ko);
                ldmx4(afl[ma], sAl + ro + ko);
            }
            uint32_t bf[4][4];
            const uint32_t bko = ks * 32 + b_kh * 16;
            // hi B: hh + lh passes
#pragma unroll
            for (int nb = 0; nb < 4; nb++)
                ldmx4(bf[nb], sBh + (uint32_t)(wn * 64 + nb * 16 + b_row) * ROWB + bko);
#pragma unroll
            for (int ma = 0; ma < 2; ma++)
#pragma unroll
                for (int nb = 0; nb < 4; nb++) {
                    mma16816(acc[ma][2 * nb],     afh[ma], &bf[nb][0]);
                    mma16816(acc[ma][2 * nb + 1], afh[ma], &bf[nb][2]);
                    mma16816(acc[ma][2 * nb],     afl[ma], &bf[nb][0]);
                    mma16816(acc[ma][2 * nb + 1], afl[ma], &bf[nb][2]);
                }
            // lo B: hl pass (reuse bf regs)
#pragma unroll
            for (int nb = 0; nb < 4; nb++)
                ldmx4(bf[nb], sBl + (uint32_t)(wn * 64 + nb * 16 + b_row) * ROWB + bko);
#pragma unroll
            for (int ma = 0; ma < 2; ma++)
#pragma unroll
                for (int nb = 0; nb < 4; nb++) {
                    mma16816(acc[ma][2 * nb],     afh[ma], &bf[nb][0]);
                    mma16816(acc[ma][2 * nb + 1], afh[ma], &bf[nb][2]);
                }
        }
    };

    load_chunk(0, 0);
    for (int i = 0; i < nchunk; i++) {
        if (i + 1 < nchunk) {
            load_chunk(i + 1, (i + 1) & 1);
            asm volatile("cp.async.wait_group 1;" ::: "memory");
        } else {
            asm volatile("cp.async.wait_group 0;" ::: "memory");
        }
        __syncthreads();
        compute(i & 1);
        __syncthreads();
    }

    // ---- epilogue ----
#pragma unroll
    for (int ma = 0; ma < 2; ma++) {
        const int r0 = bm + wm * 32 + ma * 16 + (lane >> 2);
        const int cb = bn + wn * 64 + 2 * (lane & 3);
#pragma unroll
        for (int half = 0; half < 2; half++) {
            float* crow = C + (size_t)(r0 + half * 8) * N + cb;
#pragma unroll
            for (int na = 0; na < 8; na++)
                *(float2*)(crow + na * 8) =
                    make_float2(acc[ma][na][half * 2], acc[ma][na][half * 2 + 1]);
        }
    }
}

// ============================================================================
// fp32 -> (hi, lo) bf16 split, float4-vectorized
// ============================================================================
__global__ __launch_bounds__(256) void split_bf16(const float* __restrict__ in,
                                                  __nv_bfloat16* __restrict__ hi,
                                                  __nv_bfloat16* __restrict__ lo,
                                                  int n4) {
    int i = blockIdx.x * 256 + threadIdx.x;
    if (i >= n4) return;
    float4 v = ((const float4*)in)[i];
    float vs[4] = {v.x, v.y, v.z, v.w};
    uint32_t hp[2], lp[2];
#pragma unroll
    for (int j = 0; j < 2; j++) {
        __nv_bfloat16 h0 = __float2bfloat16(vs[2 * j]);
        __nv_bfloat16 h1 = __float2bfloat16(vs[2 * j + 1]);
        __nv_bfloat16 l0 = __float2bfloat16(vs[2 * j] - __bfloat162float(h0));
        __nv_bfloat16 l1 = __float2bfloat16(vs[2 * j + 1] - __bfloat162float(h1));
        hp[j] = (uint32_t)__bfloat16_as_ushort(h0) |
                ((uint32_t)__bfloat16_as_ushort(h1) << 16);
        lp[j] = (uint32_t)__bfloat16_as_ushort(l0) |
                ((uint32_t)__bfloat16_as_ushort(l1) << 16);
    }
    ((uint2*)hi)[i] = make_uint2(hp[0], hp[1]);
    ((uint2*)lo)[i] = make_uint2(lp[0], lp[1]);
}

// ============================================================================
// RoPE + split + [h][s][d] transpose
// ============================================================================
__global__ __launch_bounds__(256) void rope_split(const float* __restrict__ qkv,
                                                  const float* __restrict__ cosb,
                                                  const float* __restrict__ sinb) {
    int idx = blockIdx.x * 256 + threadIdx.x;
    if (idx >= S_LEN * QKV_OUT) return;
    int s = idx / QKV_OUT;
    int o = idx - s * QKV_OUT;
    int hh = o >> 6;
    int d  = o & 63;
    float val = qkv[idx];
    if (hh < NH + NKV) {
        float c  = cosb[s * HD + d];
        float sn = sinb[s * HD + d];
        int dpair = (d < 32) ? d + 32 : d - 32;
        float other = qkv[s * QKV_OUT + (hh << 6) + dpair];
        float rot = (d < 32) ? -other : other;
        float r = val * c + rot * sn;
        if (hh < NH) g_q[((hh * S_LEN + s) << 6) + d] = r;
        else         g_k[(((hh - NH) * S_LEN + s) << 6) + d] = r;
    } else {
        g_v[(((hh - NH - NKV) * S_LEN + s) << 6) + d] = val;
    }
}

// ============================================================================
// fp32 flash attention, causal, GQA (unchanged)
// ============================================================================
#define PADT 68
#define ATTN_SMEM ((3 * 64 * PADT + 64 * 64) * 4)

__global__ __launch_bounds__(256) void flash_attn(float* __restrict__ Og) {
    extern __shared__ float sm[];
    float* Qs = sm;
    float* Ks = Qs + 64 * PADT;
    float* Ps = Ks + 64 * PADT;
    float* Vs = Ps + 64 * PADT;

    const int qb = blockIdx.x;
    const int h  = blockIdx.y;
    const float* Qh = g_q + (size_t)(h * S_LEN + qb * 64) * HD;
    const float* Kh = g_k + (size_t)((h >> 2) * S_LEN) * HD;
    const float* Vh = g_v + (size_t)((h >> 2) * S_LEN) * HD;

    const int tid = threadIdx.x;
    const int lr  = tid >> 4;
    const int ld4 = (tid & 15) << 2;
    const int ty = tid >> 4, tx = tid & 15;
    const int tr = ty << 2, tc = tx << 2;

#pragma unroll
    for (int it = 0; it < 4; it++) {
        int r = lr + it * 16;
        float4 qv = *(const float4*)(Qh + r * HD + ld4);
        Qs[(ld4 + 0) * PADT + r] = qv.x;
        Qs[(ld4 + 1) * PADT + r] = qv.y;
        Qs[(ld4 + 2) * PADT + r] = qv.z;
        Qs[(ld4 + 3) * PADT + r] = qv.w;
    }

    float m[4], l[4], o[4][4];
#pragma unroll
    for (int i = 0; i < 4; i++) {
        m[i] = -1e30f; l[i] = 0.f;
#pragma unroll
        for (int j = 0; j < 4; j++) o[i][j] = 0.f;
    }
    __syncthreads();

    const float scale = 0.125f;
    const unsigned FULL = 0xffffffffu;

    for (int kb = 0; kb <= qb; kb++) {
#pragma unroll
        for (int it = 0; it < 4; it++) {
            int r = lr + it * 16;
            float4 kv = *(const float4*)(Kh + (size_t)(kb * 64 + r) * HD + ld4);
            Ks[(ld4 + 0) * PADT + r] = kv.x;
            Ks[(ld4 + 1) * PADT + r] = kv.y;
            Ks[(ld4 + 2) * PADT + r] = kv.z;
            Ks[(ld4 + 3) * PADT + r] = kv.w;
            float4 vv = *(const float4*)(Vh + (size_t)(kb * 64 + r) * HD + ld4);
            *(float4*)&Vs[r * 64 + ld4] = vv;
        }
        __syncthreads();

        float s4[4][4];
#pragma unroll
        for (int i = 0; i < 4; i++)
#pragma unroll
            for (int j = 0; j < 4; j++) s4[i][j] = 0.f;
#pragma unroll 16
        for (int d = 0; d < 64; d++) {
            float4 a = *(const float4*)&Qs[d * PADT + tr];
            float4 b = *(const float4*)&Ks[d * PADT + tc];
            float av[4] = {a.x, a.y, a.z, a.w};
            float bv[4] = {b.x, b.y, b.z, b.w};
#pragma unroll
            for (int i = 0; i < 4; i++)
#pragma unroll
                for (int j = 0; j < 4; j++)
                    s4[i][j] += av[i] * bv[j];
        }

        if (kb == qb) {
#pragma unroll
            for (int i = 0; i < 4; i++)
#pragma unroll
                for (int j = 0; j < 4; j++)
                    s4[i][j] = (tc + j > tr + i) ? -1e30f : s4[i][j] * scale;
        } else {
#pragma unroll
            for (int i = 0; i < 4; i++)
#pragma unroll
                for (int j = 0; j < 4; j++) s4[i][j] *= scale;
        }

        float p[4][4];
#pragma unroll
        for (int i = 0; i < 4; i++) {
            float mt = fmaxf(fmaxf(s4[i][0], s4[i][1]), fmaxf(s4[i][2], s4[i][3]));
#pragma unroll
            for (int off = 8; off >= 1; off >>= 1)
                mt = fmaxf(mt, __shfl_xor_sync(FULL, mt, off));
            float mn = fmaxf(m[i], mt);
            float corr = __expf(m[i] - mn);
            float rs = 0.f;
#pragma unroll
            for (int j = 0; j < 4; j++) {
                p[i][j] = __expf(s4[i][j] - mn);
                rs += p[i][j];
            }
#pragma unroll
            for (int off = 8; off >= 1; off >>= 1)
                rs += __shfl_xor_sync(FULL, rs, off);
            l[i] = l[i] * corr + rs;
            m[i] = mn;
#pragma unroll
            for (int j = 0; j < 4; j++) o[i][j] *= corr;
        }

        __syncthreads();
#pragma unroll
        for (int i = 0; i < 4; i++)
#pragma unroll
            for (int j = 0; j < 4; j++)
                Ps[(tc + j) * PADT + (tr + i)] = p[i][j];
        __syncthreads();

#pragma unroll 16
        for (int j = 0; j < 64; j++) {
            float4 a = *(const float4*)&Ps[j * PADT + tr];
            float4 b = *(const float4*)&Vs[j * 64 + tc];
            float av[4] = {a.x, a.y, a.z, a.w};
            float bv[4] = {b.x, b.y, b.z, b.w};
#pragma unroll
            for (int i = 0; i < 4; i++)
#pragma unroll
                for (int jj = 0; jj < 4; jj++)
                    o[i][jj] += av[i] * bv[jj];
        }
        __syncthreads();
    }

#pragma unroll
    for (int i = 0; i < 4; i++) {
        float inv = 1.f / l[i];
        float4 outv = make_float4(o[i][0] * inv, o[i][1] * inv,
                                  o[i][2] * inv, o[i][3] * inv);
        *(float4*)&Og[(size_t)(qb * 64 + tr + i) * (NH * HD) + h * HD + tc] = outv;
    }
}

// =====================================================================
extern "C" void kernel_launch(void* const* d_in, const int* in_sizes, int n_in,
                              void* d_out, int out_size) {
    const float* x     = (const float*)d_in[0];
    const float* cosb  = (const float*)d_in[1];
    const float* sinb  = (const float*)d_in[2];
    const float* w_qkv = (const float*)d_in[3];
    const float* w_out = (const float*)d_in[4];
    float* out = (float*)d_out;

    float *qkv_p, *attn_p;
    cudaGetSymbolAddress((void**)&qkv_p, g_qkv);
    cudaGetSymbolAddress((void**)&attn_p, g_attn);
    __nv_bfloat16 *xh, *xl, *wqh, *wql, *woh, *wol, *ah, *al;
    cudaGetSymbolAddress((void**)&xh, g_xh);
    cudaGetSymbolAddress((void**)&xl, g_xl);
    cudaGetSymbolAddress((void**)&wqh, g_wqh);
    cudaGetSymbolAddress((void**)&wql, g_wql);
    cudaGetSymbolAddress((void**)&woh, g_woh);
    cudaGetSymbolAddress((void**)&wol, g_wol);
    cudaGetSymbolAddress((void**)&ah, g_ah);
    cudaGetSymbolAddress((void**)&al, g_al);

    cudaFuncSetAttribute(flash_attn, cudaFuncAttributeMaxDynamicSharedMemorySize,
                         ATTN_SMEM);
    cudaFuncSetAttribute(gemm_mma, cudaFuncAttributeMaxDynamicSharedMemorySize,
                         GEMM_SMEM);

    // 0) fp32 -> bf16 hi/lo splits
    split_bf16<<<(S_LEN * HID / 4 + 255) / 256, 256>>>(x, xh, xl, S_LEN * HID / 4);
    split_bf16<<<(QKV_OUT * HID / 4 + 255) / 256, 256>>>(w_qkv, wqh, wql,
                                                         QKV_OUT * HID / 4);
    split_bf16<<<(HID * HID / 4 + 255) / 256, 256>>>(w_out, woh, wol,
                                                     HID * HID / 4);

    // 1) QKV projection (mma.sync bf16 split): [2048,3072] = x @ w_qkv^T
    gemm_mma<<<dim3(QKV_OUT / 128, S_LEN / 128), 256, GEMM_SMEM>>>(
        xh, xl, wqh, wql, qkv_p, QKV_OUT, HID);
    // 2) RoPE + split + transpose
    rope_split<<<(S_LEN * QKV_OUT + 255) / 256, 256>>>(qkv_p, cosb, sinb);
    // 3) causal flash attention (fp32)
    flash_attn<<<dim3(S_LEN / 64, NH), 256, ATTN_SMEM>>>(attn_p);
    // 4) split attention output, then out-projection
    split_bf16<<<(S_LEN * HID / 4 + 255) / 256, 256>>>(attn_p, ah, al,
                                                       S_LEN * HID / 4);
    gemm_mma<<<dim3(HID / 128, S_LEN / 128), 256, GEMM_SMEM>>>(
        ah, al, woh, wol, out, HID, NH * HD);
}

// round 5
// speedup vs baseline: 3.0700x; 1.7125x over previous
#include <cuda_runtime.h>
#include <cuda_fp16.h>
#include <cstdint>

#define S_LEN 2048
#define HID 2048
#define NH 32
#define NKV 8
#define HD 64
#define QKV_OUT 3072   // (32 + 2*8) * 64

// ---------------- scratch (static device globals; no allocation) ----------------
__device__ float g_qkv[S_LEN * QKV_OUT];                    // fp32 qkv
__device__ __align__(16) __half g_xh[S_LEN * HID],  g_xl[S_LEN * HID];
__device__ __align__(16) __half g_wqh[QKV_OUT * HID], g_wql[QKV_OUT * HID];
__device__ __align__(16) __half g_woh[HID * HID],   g_wol[HID * HID];
__device__ __align__(16) __half g_qhh[NH * S_LEN * HD],  g_qhl[NH * S_LEN * HD];
__device__ __align__(16) __half g_khh[NKV * S_LEN * HD], g_khl[NKV * S_LEN * HD];
__device__ __align__(16) __half g_vhh[NKV * S_LEN * HD], g_vhl[NKV * S_LEN * HD];
__device__ __align__(16) __half g_ahh[S_LEN * HID], g_ahl[S_LEN * HID];

// ============================ helpers ============================
__device__ __forceinline__ uint32_t smem_u32(const void* p) {
    uint32_t a;
    asm("{ .reg .u64 t; cvta.to.shared.u64 t, %1; cvt.u32.u64 %0, t; }"
        : "=r"(a) : "l"(p));
    return a;
}
__device__ __forceinline__ void cp16(uint32_t s, const void* g) {
    asm volatile("cp.async.cg.shared.global [%0], [%1], 16;" :: "r"(s), "l"(g));
}
#define CP_COMMIT() asm volatile("cp.async.commit_group;" ::: "memory")

__device__ __forceinline__ void ldmx4(uint32_t* r, uint32_t addr) {
    asm volatile("ldmatrix.sync.aligned.m8n8.x4.shared.b16 {%0,%1,%2,%3}, [%4];"
                 : "=r"(r[0]), "=r"(r[1]), "=r"(r[2]), "=r"(r[3]) : "r"(addr));
}
__device__ __forceinline__ void ldmx4t(uint32_t* r, uint32_t addr) {
    asm volatile("ldmatrix.sync.aligned.m8n8.x4.trans.shared.b16 {%0,%1,%2,%3}, [%4];"
                 : "=r"(r[0]), "=r"(r[1]), "=r"(r[2]), "=r"(r[3]) : "r"(addr));
}
__device__ __forceinline__ void mma_h(float* d, const uint32_t* a,
                                      const uint32_t* b) {
    asm volatile(
        "mma.sync.aligned.m16n8k16.row.col.f32.f16.f16.f32 "
        "{%0,%1,%2,%3}, {%4,%5,%6,%7}, {%8,%9}, {%0,%1,%2,%3};"
        : "+f"(d[0]), "+f"(d[1]), "+f"(d[2]), "+f"(d[3])
        : "r"(a[0]), "r"(a[1]), "r"(a[2]), "r"(a[3]), "r"(b[0]), "r"(b[1]));
}
__device__ __forceinline__ float ex2(float x) {
    float y;
    asm("ex2.approx.ftz.f32 %0, %1;" : "=f"(y) : "f"(x));
    return y;
}
__device__ __forceinline__ uint32_t packh2(float a, float b) {
    __half2 h = __floats2half2_rn(a, b);
    return *(uint32_t*)&h;
}
// split two fp32 values into packed (hi2, lo2) fp16 pairs
__device__ __forceinline__ void split2(float a, float b, uint32_t& hp, uint32_t& lp) {
    __half ha = __float2half_rn(a), hb = __float2half_rn(b);
    hp = (uint32_t)__half_as_ushort(ha) | ((uint32_t)__half_as_ushort(hb) << 16);
    __half la = __float2half_rn(a - __half2float(ha));
    __half lb = __float2half_rn(b - __half2float(hb));
    lp = (uint32_t)__half_as_ushort(la) | ((uint32_t)__half_as_ushort(lb) << 16);
}

// ============================================================================
// fp16 split-precision GEMM (3-pass: AhBh + AhBl + AlBh), fp32 accumulate.
// C[M,N] = A[M,K]*B[N,K]^T. 128x128 CTA tile, BK=32, 8 warps (4x2).
// ============================================================================
#define BK 32
#define ROWB 80
#define TILE_B (128 * ROWB)             // 10240
#define STAGE_B (4 * TILE_B)            // Ah, Al, Bh, Bl = 40960
#define GEMM_SMEM (2 * STAGE_B)         // 81920

__global__ __launch_bounds__(256, 2) void gemm_hs(
    const __half* __restrict__ Ah, const __half* __restrict__ Al,
    const __half* __restrict__ Bh, const __half* __restrict__ Bl,
    float* __restrict__ C, int N, int K) {
    extern __shared__ __align__(128) char dsm[];
    const uint32_t base = smem_u32(dsm);

    const int tid = threadIdx.x;
    const int wid = tid >> 5;
    const int lane = tid & 31;
    const int wm = wid >> 1;
    const int wn = wid & 1;
    const int bm = blockIdx.y * 128;
    const int bn = blockIdx.x * 128;
    const int nchunk = K / BK;

    float acc[2][8][4];
#pragma unroll
    for (int i = 0; i < 2; i++)
#pragma unroll
        for (int j = 0; j < 8; j++)
#pragma unroll
            for (int k = 0; k < 4; k++) acc[i][j][k] = 0.f;

    auto load_chunk = [&](int chunk, int stage) {
        const int k0 = chunk * BK;
        const uint32_t sb = base + stage * STAGE_B;
#pragma unroll
        for (int t = 0; t < 4; t++) {
            const __half* src = (t == 0) ? Ah : (t == 1) ? Al : (t == 2) ? Bh : Bl;
            const int rowbase = (t < 2) ? bm : bn;
            const uint32_t tb = sb + t * TILE_B;
#pragma unroll
            for (int i = 0; i < 2; i++) {
                int c = tid + i * 256;
                int r = c >> 2;
                int cc = c & 3;
                cp16(tb + r * ROWB + cc * 16,
                     src + (size_t)(rowbase + r) * K + k0 + cc * 8);
            }
        }
        CP_COMMIT();
    };

    const int a_row = lane & 15;
    const int a_kh  = lane >> 4;
    const int b_row = (lane & 7) + ((lane >> 4) << 3);
    const int b_kh  = (lane >> 3) & 1;

    auto compute = [&](int stage) {
        const uint32_t sb  = base + stage * STAGE_B;
        const uint32_t sAh = sb;
        const uint32_t sAl = sb + TILE_B;
        const uint32_t sBh = sb + 2 * TILE_B;
        const uint32_t sBl = sb + 3 * TILE_B;
#pragma unroll
        for (int ks = 0; ks < 2; ks++) {
            const uint32_t ko = ks * 32 + a_kh * 16;
            uint32_t afh[2][4], afl[2][4];
#pragma unroll
            for (int ma = 0; ma < 2; ma++) {
                const uint32_t ro = (uint32_t)(wm * 32 + ma * 16 + a_row) * ROWB;
                ldmx4(afh[ma], sAh + ro + ko);
                ldmx4(afl[ma], sAl + ro + ko);
            }
            const uint32_t bko = ks * 32 + b_kh * 16;
#pragma unroll
            for (int nb = 0; nb < 4; nb++) {
                uint32_t bf[4];
                ldmx4(bf, sBh + (uint32_t)(wn * 64 + nb * 16 + b_row) * ROWB + bko);
#pragma unroll
                for (int ma = 0; ma < 2; ma++) {
                    mma_h(acc[ma][2 * nb],     afh[ma], bf);
                    mma_h(acc[ma][2 * nb + 1], afh[ma], bf + 2);
                    mma_h(acc[ma][2 * nb],     afl[ma], bf);
                    mma_h(acc[ma][2 * nb + 1], afl[ma], bf + 2);
                }
            }
#pragma unroll
            for (int nb = 0; nb < 4; nb++) {
                uint32_t bf[4];
                ldmx4(bf, sBl + (uint32_t)(wn * 64 + nb * 16 + b_row) * ROWB + bko);
#pragma unroll
                for (int ma = 0; ma < 2; ma++) {
                    mma_h(acc[ma][2 * nb],     afh[ma], bf);
                    mma_h(acc[ma][2 * nb + 1], afh[ma], bf + 2);
                }
            }
        }
    };

    load_chunk(0, 0);
    for (int i = 0; i < nchunk; i++) {
        if (i + 1 < nchunk) {
            load_chunk(i + 1, (i + 1) & 1);
            asm volatile("cp.async.wait_group 1;" ::: "memory");
        } else {
            asm volatile("cp.async.wait_group 0;" ::: "memory");
        }
        __syncthreads();
        compute(i & 1);
        __syncthreads();
    }

#pragma unroll
    for (int ma = 0; ma < 2; ma++) {
        const int r0 = bm + wm * 32 + ma * 16 + (lane >> 2);
        const int cb = bn + wn * 64 + 2 * (lane & 3);
#pragma unroll
        for (int half = 0; half < 2; half++) {
            float* crow = C + (size_t)(r0 + half * 8) * N + cb;
#pragma unroll
            for (int na = 0; na < 8; na++)
                *(float2*)(crow + na * 8) =
                    make_float2(acc[ma][na][half * 2], acc[ma][na][half * 2 + 1]);
        }
    }
}

// ============================================================================
// fp32 -> (hi, lo) fp16 split, float4-vectorized
// ============================================================================
__global__ __launch_bounds__(256) void split_h(const float* __restrict__ in,
                                               __half* __restrict__ hi,
                                               __half* __restrict__ lo, int n4) {
    int i = blockIdx.x * 256 + threadIdx.x;
    if (i >= n4) return;
    float4 v = ((const float4*)in)[i];
    uint32_t h0, l0, h1, l1;
    split2(v.x, v.y, h0, l0);
    split2(v.z, v.w, h1, l1);
    ((uint2*)hi)[i] = make_uint2(h0, h1);
    ((uint2*)lo)[i] = make_uint2(l0, l1);
}

// ============================================================================
// RoPE + split + [h][s][d] transpose; fp32 in, fp16 hi/lo out
// ============================================================================
__global__ __launch_bounds__(256) void rope_split_s(const float* __restrict__ qkv,
                                                    const float* __restrict__ cosb,
                                                    const float* __restrict__ sinb) {
    int idx = blockIdx.x * 256 + threadIdx.x;
    if (idx >= S_LEN * QKV_OUT) return;
    int s = idx / QKV_OUT;
    int o = idx - s * QKV_OUT;
    int hh = o >> 6;
    int d  = o & 63;
    float val = qkv[idx];
    float r;
    if (hh < NH + NKV) {
        float c  = cosb[s * HD + d];
        float sn = sinb[s * HD + d];
        int dpair = (d < 32) ? d + 32 : d - 32;
        float other = qkv[s * QKV_OUT + (hh << 6) + dpair];
        float rot = (d < 32) ? -other : other;
        r = val * c + rot * sn;
    } else {
        r = val;
    }
    __half h = __float2half_rn(r);
    __half l = __float2half_rn(r - __half2float(h));
    if (hh < NH) {
        int a = ((hh * S_LEN + s) << 6) + d;
        g_qhh[a] = h; g_qhl[a] = l;
    } else if (hh < NH + NKV) {
        int a = (((hh - NH) * S_LEN + s) << 6) + d;
        g_khh[a] = h; g_khl[a] = l;
    } else {
        int a = (((hh - NH - NKV) * S_LEN + s) << 6) + d;
        g_vhh[a] = h; g_vhl[a] = l;
    }
}

// ============================================================================
// fp16 split-precision (3-pass) flash attention, causal, GQA.
// grid (16 qb, 32 h); 256 thr = 8 warps x 16 q-rows. Q tile 128, KV tiles 64.
// Q/K split in S; P (in-register split) / V split in PV. Online softmax exp2.
// ============================================================================
#define AROWB 144                        // 128B data + 16B pad
#define AQ_B   (128 * AROWB)             // 18432 per Q tile
#define AKV_B  (64 * AROWB)              // 9216 per KV tile
#define AST_B  (4 * AKV_B)               // Kh,Kl,Vh,Vl = 36864
#define ATTN_SMEM (2 * AQ_B + 2 * AST_B) // 110592

__global__ __launch_bounds__(256, 1) void flash_attn_s() {
    extern __shared__ __align__(128) char dsm[];
    const uint32_t base = smem_u32(dsm);
    const uint32_t sQh = base;
    const uint32_t sQl = base + AQ_B;
    const uint32_t ringb = base + 2 * AQ_B;

    const int qb = 15 - (int)blockIdx.x;     // heavy CTAs first
    const int h  = blockIdx.y;
    const __half* Qhg = g_qhh + (size_t)(h * S_LEN + qb * 128) * HD;
    const __half* Qlg = g_qhl + (size_t)(h * S_LEN + qb * 128) * HD;
    const size_t kvo = (size_t)((h >> 2) * S_LEN) * HD;
    const __half* Khg = g_khh + kvo;
    const __half* Klg = g_khl + kvo;
    const __half* Vhg = g_vhh + kvo;
    const __half* Vlg = g_vhl + kvo;

    const int tid = threadIdx.x;
    const int wq = tid >> 5;
    const int lane = tid & 31;

    // ---- Q hi/lo loads ----
#pragma unroll
    for (int i = 0; i < 4; i++) {
        int c = tid + i * 256;
        int r = c >> 3, c8 = c & 7;
        cp16(sQh + r * AROWB + c8 * 16, Qhg + r * HD + c8 * 8);
        cp16(sQl + r * AROWB + c8 * 16, Qlg + r * HD + c8 * 8);
    }
    CP_COMMIT();

    auto load_kv = [&](int kb, int st) {
        const uint32_t sb = ringb + st * AST_B;
#pragma unroll
        for (int i = 0; i < 2; i++) {
            int c = tid + i * 256;
            int r = c >> 3, c8 = c & 7;
            const size_t go = (size_t)(kb * 64 + r) * HD + c8 * 8;
            const uint32_t so = r * AROWB + c8 * 16;
            cp16(sb + so,             Khg + go);
            cp16(sb + AKV_B + so,     Klg + go);
            cp16(sb + 2 * AKV_B + so, Vhg + go);
            cp16(sb + 3 * AKV_B + so, Vlg + go);
        }
        CP_COMMIT();
    };

    const int a_row = lane & 15;
    const int a_kh  = lane >> 4;
    const int b_row = (lane & 7) + ((lane >> 4) << 3);
    const int b_kh  = (lane >> 3) & 1;
    const int v_row = (lane & 7) + ((lane >> 3) & 1) * 8;
    const int v_nh  = (lane >> 4) * 8;

    uint32_t qah[4][4], qal[4][4];
    float oacc[8][4];
    float m_lo = -1e30f, m_hi = -1e30f, l_lo = 0.f, l_hi = 0.f;
#pragma unroll
    for (int a = 0; a < 8; a++)
#pragma unroll
        for (int r = 0; r < 4; r++) oacc[a][r] = 0.f;

    const float sscale = 0.125f * 1.44269504f;   // scale * log2(e)
    const int row_lo = qb * 128 + wq * 16 + (lane >> 2);
    const int nkb = 2 * qb + 2;

    load_kv(0, 0);

    for (int i = 0; i < nkb; i++) {
        const int st = i & 1;
        if (i + 1 < nkb) {
            load_kv(i + 1, st ^ 1);
            asm volatile("cp.async.wait_group 1;" ::: "memory");
        } else {
            asm volatile("cp.async.wait_group 0;" ::: "memory");
        }
        __syncthreads();

        if (i == 0) {
#pragma unroll
            for (int ka = 0; ka < 4; ka++) {
                const uint32_t qo = (uint32_t)(wq * 16 + a_row) * AROWB +
                                    ka * 32 + a_kh * 16;
                ldmx4(qah[ka], sQh + qo);
                ldmx4(qal[ka], sQl + qo);
            }
        }

        const uint32_t sKh = ringb + st * AST_B;
        const uint32_t sKl = sKh + AKV_B;
        const uint32_t sVh = sKh + 2 * AKV_B;
        const uint32_t sVl = sKh + 3 * AKV_B;

        // ---- S = Q K^T  (3-pass: QhKh + QhKl + QlKh) ----
        float sacc[8][4];
#pragma unroll
        for (int a = 0; a < 8; a++)
#pragma unroll
            for (int r = 0; r < 4; r++) sacc[a][r] = 0.f;
#pragma unroll
        for (int ka = 0; ka < 4; ka++) {
            const uint32_t bko = ka * 32 + b_kh * 16;
#pragma unroll
            for (int nb = 0; nb < 4; nb++) {
                const uint32_t ro = (uint32_t)(nb * 16 + b_row) * AROWB + bko;
                uint32_t bh[4], bl[4];
                ldmx4(bh, sKh + ro);
                ldmx4(bl, sKl + ro);
                mma_h(sacc[2 * nb],     qah[ka], bh);
                mma_h(sacc[2 * nb + 1], qah[ka], bh + 2);
                mma_h(sacc[2 * nb],     qah[ka], bl);
                mma_h(sacc[2 * nb + 1], qah[ka], bl + 2);
                mma_h(sacc[2 * nb],     qal[ka], bh);
                mma_h(sacc[2 * nb + 1], qal[ka], bh + 2);
            }
        }

        // ---- scale + causal mask (exp2 domain) ----
        const bool need_mask = (i * 64 + 63) > (qb * 128 + wq * 16);
        if (need_mask) {
#pragma unroll
            for (int a = 0; a < 8; a++) {
                const int colb = i * 64 + a * 8 + 2 * (lane & 3);
#pragma unroll
                for (int r = 0; r < 4; r++) {
                    const int col = colb + (r & 1);
                    const int row = row_lo + (r >> 1) * 8;
                    sacc[a][r] = (col > row) ? -1e30f : sacc[a][r] * sscale;
                }
            }
        } else {
#pragma unroll
            for (int a = 0; a < 8; a++)
#pragma unroll
                for (int r = 0; r < 4; r++) sacc[a][r] *= sscale;
        }

        // ---- online softmax (rows lo = r0/1, hi = r2/3) ----
        float tmlo = -1e30f, tmhi = -1e30f;
#pragma unroll
        for (int a = 0; a < 8; a++) {
            tmlo = fmaxf(tmlo, fmaxf(sacc[a][0], sacc[a][1]));
            tmhi = fmaxf(tmhi, fmaxf(sacc[a][2], sacc[a][3]));
        }
#pragma unroll
        for (int off = 1; off <= 2; off <<= 1) {
            tmlo = fmaxf(tmlo, __shfl_xor_sync(0xffffffffu, tmlo, off));
            tmhi = fmaxf(tmhi, __shfl_xor_sync(0xffffffffu, tmhi, off));
        }
        const float mn_lo = fmaxf(m_lo, tmlo);
        const float mn_hi = fmaxf(m_hi, tmhi);
        const float corr_lo = ex2(m_lo - mn_lo);
        const float corr_hi = ex2(m_hi - mn_hi);
        m_lo = mn_lo; m_hi = mn_hi;

        float rs_lo = 0.f, rs_hi = 0.f;
#pragma unroll
        for (int a = 0; a < 8; a++) {
            sacc[a][0] = ex2(sacc[a][0] - mn_lo);
            sacc[a][1] = ex2(sacc[a][1] - mn_lo);
            sacc[a][2] = ex2(sacc[a][2] - mn_hi);
            sacc[a][3] = ex2(sacc[a][3] - mn_hi);
            rs_lo += sacc[a][0] + sacc[a][1];
            rs_hi += sacc[a][2] + sacc[a][3];
        }
#pragma unroll
        for (int off = 1; off <= 2; off <<= 1) {
            rs_lo += __shfl_xor_sync(0xffffffffu, rs_lo, off);
            rs_hi += __shfl_xor_sync(0xffffffffu, rs_hi, off);
        }
        l_lo = l_lo * corr_lo + rs_lo;
        l_hi = l_hi * corr_hi + rs_hi;
#pragma unroll
        for (int a = 0; a < 8; a++) {
            oacc[a][0] *= corr_lo; oacc[a][1] *= corr_lo;
            oacc[a][2] *= corr_hi; oacc[a][3] *= corr_hi;
        }

        // ---- O += P V  (3-pass: PhVh + PhVl + PlVh), P split in-register ----
#pragma unroll
        for (int ka = 0; ka < 4; ka++) {
            uint32_t pah[4], pal[4];
            split2(sacc[2 * ka][0],     sacc[2 * ka][1],     pah[0], pal[0]);
            split2(sacc[2 * ka][2],     sacc[2 * ka][3],     pah[1], pal[1]);
            split2(sacc[2 * ka + 1][0], sacc[2 * ka + 1][1], pah[2], pal[2]);
            split2(sacc[2 * ka + 1][2], sacc[2 * ka + 1][3], pah[3], pal[3]);
#pragma unroll
            for (int nd = 0; nd < 4; nd++) {
                const uint32_t vo = (uint32_t)(ka * 16 + v_row) * AROWB +
                                    (uint32_t)(nd * 16 + v_nh) * 2;
                uint32_t vh[4], vl[4];
                ldmx4t(vh, sVh + vo);
                ldmx4t(vl, sVl + vo);
                mma_h(oacc[2 * nd],     pah, vh);
                mma_h(oacc[2 * nd + 1], pah, vh + 2);
                mma_h(oacc[2 * nd],     pah, vl);
                mma_h(oacc[2 * nd + 1], pah, vl + 2);
                mma_h(oacc[2 * nd],     pal, vh);
                mma_h(oacc[2 * nd + 1], pal, vh + 2);
            }
        }
        __syncthreads();
    }

    // ---- normalize + write split fp16 to g_ahh/g_ahl [s][h*64+d] ----
    const float inv_lo = 1.f / l_lo;
    const float inv_hi = 1.f / l_hi;
    const int srow_lo = qb * 128 + wq * 16 + (lane >> 2);
#pragma unroll
    for (int a = 0; a < 8; a++) {
        const int col = h * 64 + a * 8 + 2 * (lane & 3);
        uint32_t hp, lp;
        split2(oacc[a][0] * inv_lo, oacc[a][1] * inv_lo, hp, lp);
        *(uint32_t*)(g_ahh + (size_t)srow_lo * HID + col) = hp;
        *(uint32_t*)(g_ahl + (size_t)srow_lo * HID + col) = lp;
        split2(oacc[a][2] * inv_hi, oacc[a][3] * inv_hi, hp, lp);
        *(uint32_t*)(g_ahh + (size_t)(srow_lo + 8) * HID + col) = hp;
        *(uint32_t*)(g_ahl + (size_t)(srow_lo + 8) * HID + col) = lp;
    }
}

// =====================================================================
extern "C" void kernel_launch(void* const* d_in, const int* in_sizes, int n_in,
                              void* d_out, int out_size) {
    const float* x     = (const float*)d_in[0];
    const float* cosb  = (const float*)d_in[1];
    const float* sinb  = (const float*)d_in[2];
    const float* w_qkv = (const float*)d_in[3];
    const float* w_out = (const float*)d_in[4];
    float* out = (float*)d_out;

    float* qkv_p;
    cudaGetSymbolAddress((void**)&qkv_p, g_qkv);
    __half *xh, *xl, *wqh, *wql, *woh, *wol, *ahh, *ahl;
    cudaGetSymbolAddress((void**)&xh, g_xh);
    cudaGetSymbolAddress((void**)&xl, g_xl);
    cudaGetSymbolAddress((void**)&wqh, g_wqh);
    cudaGetSymbolAddress((void**)&wql, g_wql);
    cudaGetSymbolAddress((void**)&woh, g_woh);
    cudaGetSymbolAddress((void**)&wol, g_wol);
    cudaGetSymbolAddress((void**)&ahh, g_ahh);
    cudaGetSymbolAddress((void**)&ahl, g_ahl);

    cudaFuncSetAttribute(gemm_hs, cudaFuncAttributeMaxDynamicSharedMemorySize,
                         GEMM_SMEM);
    cudaFuncSetAttribute(flash_attn_s, cudaFuncAttributeMaxDynamicSharedMemorySize,
                         ATTN_SMEM);

    // 0) fp32 -> fp16 hi/lo splits
    split_h<<<(S_LEN * HID / 4 + 255) / 256, 256>>>(x, xh, xl, S_LEN * HID / 4);
    split_h<<<(QKV_OUT * HID / 4 + 255) / 256, 256>>>(w_qkv, wqh, wql,
                                                      QKV_OUT * HID / 4);
    split_h<<<(HID * HID / 4 + 255) / 256, 256>>>(w_out, woh, wol, HID * HID / 4);

    // 1) QKV projection (3-pass fp16 split), fp32 out
    gemm_hs<<<dim3(QKV_OUT / 128, S_LEN / 128), 256, GEMM_SMEM>>>(
        xh, xl, wqh, wql, qkv_p, QKV_OUT, HID);
    // 2) RoPE + split + transpose (fp32 math, fp16 hi/lo out)
    rope_split_s<<<(S_LEN * QKV_OUT + 255) / 256, 256>>>(qkv_p, cosb, sinb);
    // 3) 3-pass fp16 split flash attention, split out
    flash_attn_s<<<dim3(16, NH), 256, ATTN_SMEM>>>();
    // 4) out-projection (3-pass fp16 split), fp32 out
    gemm_hs<<<dim3(HID / 128, S_LEN / 128), 256, GEMM_SMEM>>>(
        ahh, ahl, woh, wol, out, HID, NH * HD);
}